// round 1
// baseline (speedup 1.0000x reference)
#include <cuda_runtime.h>

#define C 1000
#define D 128
#define COLS 32            // columns per group
#define NGROUPS 4          // D / COLS
#define CHUNKS 37          // row chunks -> 4*37 = 148 CTAs = 1 wave
#define THREADS 512        // 16 warps
#define MOM 0.95f

// Scratch accumulators (allocation-free rule: __device__ globals)
__device__ float g_acc[C * D];
__device__ float g_wacc[C];

__global__ void init_kernel() {
    int i = blockIdx.x * blockDim.x + threadIdx.x;
    if (i < C * D) g_acc[i] = 0.0f;
    if (i < C)     g_wacc[i] = 0.0f;
}

__global__ void __launch_bounds__(THREADS, 1) accum_kernel(
    const float* __restrict__ feats,
    const int*   __restrict__ labels,
    const float* __restrict__ weights,
    int n)
{
    extern __shared__ float smem[];
    float* s_acc = smem;             // [C * COLS]
    float* s_w   = smem + C * COLS;  // [C]

    const int cg    = blockIdx.x % NGROUPS;   // column group
    const int chunk = blockIdx.x / NGROUPS;   // row chunk

    // zero shared accumulators
    for (int i = threadIdx.x; i < C * COLS + C; i += THREADS)
        smem[i] = 0.0f;
    __syncthreads();

    const int rpc     = (n + CHUNKS - 1) / CHUNKS;
    const int row0    = chunk * rpc;
    const int row_end = min(n, row0 + rpc);

    const int warp = threadIdx.x >> 5;
    const int lane = threadIdx.x & 31;

    const float* fbase = feats + cg * COLS + lane;

    // Each warp handles 8 consecutive rows per iteration (MLP ~ 8).
    for (int base = row0 + warp * 8; base < row_end; base += (THREADS / 32) * 8) {
        // lanes 0..7 fetch label + weight for rows base..base+7
        int   lab = 0;
        float w   = 0.0f;
        const int myrow = base + lane;
        if (lane < 8 && myrow < row_end) {
            lab = labels[myrow];
            w   = weights[myrow];
            if (lab < 0 || lab >= C) { lab = 0; w = 0.0f; }  // dtype-guess safety
        }

        // batched coalesced loads: 8 x 128B per warp
        float f[8];
#pragma unroll
        for (int k = 0; k < 8; k++) {
            int r = base + k;
            f[k] = (r < row_end) ? fbase[(long)r * D] : 0.0f;
        }

        // scatter into SMEM accumulator; lane == bank -> conflict-free RMW
#pragma unroll
        for (int k = 0; k < 8; k++) {
            int   lk = __shfl_sync(0xffffffffu, lab, k);
            float wk = __shfl_sync(0xffffffffu, w,   k);
            if (wk != 0.0f)
                atomicAdd(&s_acc[lk * COLS + lane], wk * f[k]);
        }

        // only column-group 0 accumulates the weight sums
        if (cg == 0 && lane < 8 && myrow < row_end && w != 0.0f)
            atomicAdd(&s_w[lab], w);
    }

    __syncthreads();

    // flush SMEM partials to global (sparse skip of untouched classes)
    for (int i = threadIdx.x; i < C * COLS; i += THREADS) {
        float v = s_acc[i];
        if (v != 0.0f)
            atomicAdd(&g_acc[(i >> 5) * D + cg * COLS + (i & 31)], v);
    }
    if (cg == 0) {
        for (int i = threadIdx.x; i < C; i += THREADS) {
            float v = s_w[i];
            if (v != 0.0f)
                atomicAdd(&g_wacc[i], v);
        }
    }
}

__global__ void finalize_kernel(const float* __restrict__ proto,
                                float* __restrict__ out)
{
    int i = blockIdx.x * blockDim.x + threadIdx.x;
    if (i >= C * D) return;
    int c = i >> 7;  // D == 128
    float wsum = g_wacc[c];
    float p    = proto[i];
    float vec  = g_acc[i] / fmaxf(wsum, 1e-8f);
    out[i] = (wsum > 0.0f) ? (MOM * p + (1.0f - MOM) * vec) : p;
}

extern "C" void kernel_launch(void* const* d_in, const int* in_sizes, int n_in,
                              void* d_out, int out_size)
{
    const float* feats   = (const float*)d_in[0];
    const int*   labels  = (const int*)  d_in[1];
    const float* weights = (const float*)d_in[2];
    const float* proto   = (const float*)d_in[3];
    float*       out     = (float*)d_out;

    const int n = in_sizes[1];  // labels element count == N

    const int smem_bytes = (C * COLS + C) * (int)sizeof(float);  // 132 KB
    cudaFuncSetAttribute(accum_kernel,
                         cudaFuncAttributeMaxDynamicSharedMemorySize,
                         smem_bytes);

    init_kernel<<<(C * D + 255) / 256, 256>>>();
    accum_kernel<<<NGROUPS * CHUNKS, THREADS, smem_bytes>>>(feats, labels, weights, n);
    finalize_kernel<<<(C * D + 255) / 256, 256>>>(proto, out);
}

// round 2
// speedup vs baseline: 1.7220x; 1.7220x over previous
#include <cuda_runtime.h>

#define C 1000
#define D 128
#define STRIDE 2048          // max rows per class bin (max expected ~1130)
#define MOM 0.95f

#define SCAT_THREADS 256
#define SCAT_ILP 4

#define RED_THREADS 256      // 8 warps
#define RED_WARPS 8
#define UNROLL 4

// Static scratch (allocation-free rule): zero-initialized at module load.
__device__ int  g_cursor[C];           // per-class fill cursor; reset each call
__device__ int2 g_bins[C * STRIDE];    // packed (row_index, weight_bits)

// ---------------------------------------------------------------------------
// Pass 1: bin rows by label. pos = atomicAdd(cursor[label]); store (idx, w).
// ---------------------------------------------------------------------------
__global__ void __launch_bounds__(SCAT_THREADS) scatter_kernel(
    const int*   __restrict__ labels,
    const float* __restrict__ weights,
    int n)
{
    int t    = blockIdx.x * blockDim.x + threadIdx.x;
    int base = t * SCAT_ILP;
    if (base >= n) return;

    int   lab[SCAT_ILP];
    float w[SCAT_ILP];

    if (base + SCAT_ILP <= n) {
        int4   l4 = *reinterpret_cast<const int4*>(labels + base);
        float4 w4 = *reinterpret_cast<const float4*>(weights + base);
        lab[0] = l4.x; lab[1] = l4.y; lab[2] = l4.z; lab[3] = l4.w;
        w[0] = w4.x; w[1] = w4.y; w[2] = w4.z; w[3] = w4.w;
    } else {
#pragma unroll
        for (int k = 0; k < SCAT_ILP; k++) {
            int r  = base + k;
            lab[k] = (r < n) ? labels[r]  : -1;
            w[k]   = (r < n) ? weights[r] : 0.0f;
        }
    }

#pragma unroll
    for (int k = 0; k < SCAT_ILP; k++) {
        int l = lab[k];
        if (l < 0 || l >= C) continue;
        int pos = atomicAdd(&g_cursor[l], 1);
        if (pos < STRIDE) {
            int2 e;
            e.x = base + k;
            e.y = __float_as_int(w[k]);
            g_bins[l * STRIDE + pos] = e;
        }
    }
}

// ---------------------------------------------------------------------------
// Pass 2: one CTA per class. Gather rows (contiguous 512B each), accumulate
// in registers (atomic-free), cross-warp reduce in SMEM, fused EMA epilogue.
// Resets the cursor for the next call.
// ---------------------------------------------------------------------------
__global__ void __launch_bounds__(RED_THREADS) reduce_kernel(
    const float* __restrict__ feats,
    const float* __restrict__ proto,
    float*       __restrict__ out)
{
    __shared__ float s_acc[RED_WARPS][D];
    __shared__ float s_w[RED_WARPS];

    const int c = blockIdx.x;
    int cnt = g_cursor[c];
    if (cnt > STRIDE) cnt = STRIDE;

    const int warp = threadIdx.x >> 5;
    const int lane = threadIdx.x & 31;

    float4 acc  = make_float4(0.f, 0.f, 0.f, 0.f);
    float  wsum = 0.f;

    const int2*   bin = g_bins + (size_t)c * STRIDE;
    const float4* f4  = reinterpret_cast<const float4*>(feats);

    // Warps stride in UNROLL-row batches: warp w owns rows
    // [w*U + k*8U, w*U + k*8U + U).  Batched loads give MLP ~ 4 rows/warp.
    for (int base = warp * UNROLL; base < cnt; base += RED_WARPS * UNROLL) {
        int2 e[UNROLL];
#pragma unroll
        for (int u = 0; u < UNROLL; u++) {
            int r = base + u;
            e[u] = (r < cnt) ? bin[r] : make_int2(0, 0);  // w=0 -> harmless
        }
        float4 f[UNROLL];
#pragma unroll
        for (int u = 0; u < UNROLL; u++)
            f[u] = f4[(size_t)e[u].x * (D / 4) + lane];   // coalesced 512B row
#pragma unroll
        for (int u = 0; u < UNROLL; u++) {
            float w = __int_as_float(e[u].y);
            acc.x += w * f[u].x;
            acc.y += w * f[u].y;
            acc.z += w * f[u].z;
            acc.w += w * f[u].w;
            wsum  += w;
        }
    }

    // per-warp partials -> SMEM
    reinterpret_cast<float4*>(s_acc[warp])[lane] = acc;   // STS.128
    if (lane == 0) s_w[warp] = wsum;                      // all lanes equal
    __syncthreads();

    // final reduce + fused EMA epilogue (threads 0..127 = columns)
    const int col = threadIdx.x;
    if (col < D) {
        float tot = 0.f, ws = 0.f;
#pragma unroll
        for (int k = 0; k < RED_WARPS; k++) { tot += s_acc[k][col]; ws += s_w[k]; }
        float p   = proto[c * D + col];
        float vec = tot / fmaxf(ws, 1e-8f);
        out[c * D + col] = (ws > 0.f) ? (MOM * p + (1.0f - MOM) * vec) : p;
    }

    // reset cursor for the next graph replay (zero-init covers call #1)
    if (threadIdx.x == 0) g_cursor[c] = 0;
}

extern "C" void kernel_launch(void* const* d_in, const int* in_sizes, int n_in,
                              void* d_out, int out_size)
{
    const float* feats   = (const float*)d_in[0];
    const int*   labels  = (const int*)  d_in[1];
    const float* weights = (const float*)d_in[2];
    const float* proto   = (const float*)d_in[3];
    float*       out     = (float*)d_out;

    const int n = in_sizes[1];  // labels element count == N

    const int scat_grid = (n + SCAT_THREADS * SCAT_ILP - 1) / (SCAT_THREADS * SCAT_ILP);
    scatter_kernel<<<scat_grid, SCAT_THREADS>>>(labels, weights, n);
    reduce_kernel<<<C, RED_THREADS>>>(feats, proto, out);
}

// round 3
// speedup vs baseline: 2.7519x; 1.5981x over previous
#include <cuda_runtime.h>

#define C 1000
#define D 128
#define STRIDE 2048          // max rows per class bin (max expected ~1130)
#define CPAD 64              // cursor padding: 64 ints = 256B per class ->
                             // spreads hot atomics across all LTS slices
#define MOM 0.95f

#define SCAT_THREADS 256
#define SCAT_ILP 4

#define RED_THREADS 256      // 8 warps
#define RED_WARPS 8
#define UNROLL 4

// Static scratch (allocation-free rule): zero-initialized at module load.
__device__ int  g_cursor[C * CPAD];    // per-class fill cursor at 256B stride
__device__ int2 g_bins[C * STRIDE];    // packed (row_index, weight_bits)

// ---------------------------------------------------------------------------
// Pass 1: bin rows by label. pos = atomicAdd(cursor[label]); store (idx, w).
// Cursors padded to 256B so the L2 slice hash (bits 8+) distributes them.
// ---------------------------------------------------------------------------
__global__ void __launch_bounds__(SCAT_THREADS) scatter_kernel(
    const int*   __restrict__ labels,
    const float* __restrict__ weights,
    int n)
{
    int t    = blockIdx.x * blockDim.x + threadIdx.x;
    int base = t * SCAT_ILP;
    if (base >= n) return;

    int   lab[SCAT_ILP];
    float w[SCAT_ILP];

    if (base + SCAT_ILP <= n) {
        int4   l4 = *reinterpret_cast<const int4*>(labels + base);
        float4 w4 = *reinterpret_cast<const float4*>(weights + base);
        lab[0] = l4.x; lab[1] = l4.y; lab[2] = l4.z; lab[3] = l4.w;
        w[0] = w4.x; w[1] = w4.y; w[2] = w4.z; w[3] = w4.w;
    } else {
#pragma unroll
        for (int k = 0; k < SCAT_ILP; k++) {
            int r  = base + k;
            lab[k] = (r < n) ? labels[r]  : -1;
            w[k]   = (r < n) ? weights[r] : 0.0f;
        }
    }

#pragma unroll
    for (int k = 0; k < SCAT_ILP; k++) {
        int l = lab[k];
        if (l < 0 || l >= C) continue;
        int pos = atomicAdd(&g_cursor[l * CPAD], 1);
        if (pos < STRIDE) {
            int2 e;
            e.x = base + k;
            e.y = __float_as_int(w[k]);
            g_bins[l * STRIDE + pos] = e;
        }
    }
}

// ---------------------------------------------------------------------------
// Pass 2: one CTA per class. Gather rows (contiguous 512B each), accumulate
// in registers (atomic-free), cross-warp reduce in SMEM, fused EMA epilogue.
// Resets the cursor for the next call.
// ---------------------------------------------------------------------------
__global__ void __launch_bounds__(RED_THREADS) reduce_kernel(
    const float* __restrict__ feats,
    const float* __restrict__ proto,
    float*       __restrict__ out)
{
    __shared__ float s_acc[RED_WARPS][D];
    __shared__ float s_w[RED_WARPS];

    const int c = blockIdx.x;
    int cnt = g_cursor[c * CPAD];
    if (cnt > STRIDE) cnt = STRIDE;

    const int warp = threadIdx.x >> 5;
    const int lane = threadIdx.x & 31;

    float4 acc  = make_float4(0.f, 0.f, 0.f, 0.f);
    float  wsum = 0.f;

    const int2*   bin = g_bins + (size_t)c * STRIDE;
    const float4* f4  = reinterpret_cast<const float4*>(feats);

    // Warps stride in UNROLL-row batches; batched loads give MLP ~ 4 rows/warp.
    for (int base = warp * UNROLL; base < cnt; base += RED_WARPS * UNROLL) {
        int2 e[UNROLL];
#pragma unroll
        for (int u = 0; u < UNROLL; u++) {
            int r = base + u;
            e[u] = (r < cnt) ? bin[r] : make_int2(0, 0);  // w=0 -> harmless
        }
        float4 f[UNROLL];
#pragma unroll
        for (int u = 0; u < UNROLL; u++)
            f[u] = f4[(size_t)e[u].x * (D / 4) + lane];   // coalesced 512B row
#pragma unroll
        for (int u = 0; u < UNROLL; u++) {
            float w = __int_as_float(e[u].y);
            acc.x += w * f[u].x;
            acc.y += w * f[u].y;
            acc.z += w * f[u].z;
            acc.w += w * f[u].w;
            wsum  += w;
        }
    }

    // per-warp partials -> SMEM
    reinterpret_cast<float4*>(s_acc[warp])[lane] = acc;   // STS.128
    if (lane == 0) s_w[warp] = wsum;                      // all lanes equal
    __syncthreads();

    // final reduce + fused EMA epilogue (threads 0..127 = columns)
    const int col = threadIdx.x;
    if (col < D) {
        float tot = 0.f, ws = 0.f;
#pragma unroll
        for (int k = 0; k < RED_WARPS; k++) { tot += s_acc[k][col]; ws += s_w[k]; }
        float p   = proto[c * D + col];
        float vec = tot / fmaxf(ws, 1e-8f);
        out[c * D + col] = (ws > 0.f) ? (MOM * p + (1.0f - MOM) * vec) : p;
    }

    // reset cursor for the next graph replay (zero-init covers call #1)
    if (threadIdx.x == 0) g_cursor[c * CPAD] = 0;
}

extern "C" void kernel_launch(void* const* d_in, const int* in_sizes, int n_in,
                              void* d_out, int out_size)
{
    const float* feats   = (const float*)d_in[0];
    const int*   labels  = (const int*)  d_in[1];
    const float* weights = (const float*)d_in[2];
    const float* proto   = (const float*)d_in[3];
    float*       out     = (float*)d_out;

    const int n = in_sizes[1];  // labels element count == N

    const int scat_grid = (n + SCAT_THREADS * SCAT_ILP - 1) / (SCAT_THREADS * SCAT_ILP);
    scatter_kernel<<<scat_grid, SCAT_THREADS>>>(labels, weights, n);
    reduce_kernel<<<C, RED_THREADS>>>(feats, proto, out);
}

// round 4
// speedup vs baseline: 2.7905x; 1.0140x over previous
#include <cuda_runtime.h>

#define C 1000
#define D 128
#define STRIDE 2048          // max rows per class bin (max expected ~1130)
#define CPAD 64              // cursor padding: 64 ints = 256B per class ->
                             // spreads hot atomics across all LTS slices
#define MOM 0.95f

#define SCAT_THREADS 256
#define SCAT_ILP 4

#define RED_THREADS 256      // 8 warps
#define RED_WARPS 8
#define UNROLL 4

// Static scratch (allocation-free rule): zero-initialized at module load.
__device__ int  g_cursor[C * CPAD];    // per-class fill cursor at 256B stride
__device__ int2 g_bins[C * STRIDE];    // packed (row_index, weight_bits)

// ---------------------------------------------------------------------------
// Pass 1: bin rows by label. pos = atomicAdd(cursor[label]); store (idx, w).
// Cursors padded to 256B so the L2 slice hash (bits 8+) distributes them.
// ---------------------------------------------------------------------------
__global__ void __launch_bounds__(SCAT_THREADS) scatter_kernel(
    const int*   __restrict__ labels,
    const float* __restrict__ weights,
    int n)
{
    int t    = blockIdx.x * blockDim.x + threadIdx.x;
    int base = t * SCAT_ILP;
    if (base >= n) return;

    int   lab[SCAT_ILP];
    float w[SCAT_ILP];

    if (base + SCAT_ILP <= n) {
        int4   l4 = *reinterpret_cast<const int4*>(labels + base);
        float4 w4 = *reinterpret_cast<const float4*>(weights + base);
        lab[0] = l4.x; lab[1] = l4.y; lab[2] = l4.z; lab[3] = l4.w;
        w[0] = w4.x; w[1] = w4.y; w[2] = w4.z; w[3] = w4.w;
    } else {
#pragma unroll
        for (int k = 0; k < SCAT_ILP; k++) {
            int r  = base + k;
            lab[k] = (r < n) ? labels[r]  : -1;
            w[k]   = (r < n) ? weights[r] : 0.0f;
        }
    }

#pragma unroll
    for (int k = 0; k < SCAT_ILP; k++) {
        int l = lab[k];
        if (l < 0 || l >= C) continue;
        int pos = atomicAdd(&g_cursor[l * CPAD], 1);
        if (pos < STRIDE) {
            int2 e;
            e.x = base + k;
            e.y = __float_as_int(w[k]);
            g_bins[l * STRIDE + pos] = e;
        }
    }
}

// ---------------------------------------------------------------------------
// Pass 2: one CTA per class. Gather rows (contiguous 512B each), accumulate
// in registers (atomic-free), cross-warp reduce in SMEM, fused EMA epilogue.
// Resets the cursor for the next call.
// ---------------------------------------------------------------------------
__global__ void __launch_bounds__(RED_THREADS) reduce_kernel(
    const float* __restrict__ feats,
    const float* __restrict__ proto,
    float*       __restrict__ out)
{
    __shared__ float s_acc[RED_WARPS][D];
    __shared__ float s_w[RED_WARPS];

    const int c = blockIdx.x;
    int cnt = g_cursor[c * CPAD];
    if (cnt > STRIDE) cnt = STRIDE;

    const int warp = threadIdx.x >> 5;
    const int lane = threadIdx.x & 31;

    float4 acc  = make_float4(0.f, 0.f, 0.f, 0.f);
    float  wsum = 0.f;

    const int2*   bin = g_bins + (size_t)c * STRIDE;
    const float4* f4  = reinterpret_cast<const float4*>(feats);

    // Warps stride in UNROLL-row batches; batched loads give MLP ~ 4 rows/warp.
    for (int base = warp * UNROLL; base < cnt; base += RED_WARPS * UNROLL) {
        int2 e[UNROLL];
#pragma unroll
        for (int u = 0; u < UNROLL; u++) {
            int r = base + u;
            e[u] = (r < cnt) ? bin[r] : make_int2(0, 0);  // w=0 -> harmless
        }
        float4 f[UNROLL];
#pragma unroll
        for (int u = 0; u < UNROLL; u++)
            f[u] = f4[(size_t)e[u].x * (D / 4) + lane];   // coalesced 512B row
#pragma unroll
        for (int u = 0; u < UNROLL; u++) {
            float w = __int_as_float(e[u].y);
            acc.x += w * f[u].x;
            acc.y += w * f[u].y;
            acc.z += w * f[u].z;
            acc.w += w * f[u].w;
            wsum  += w;
        }
    }

    // per-warp partials -> SMEM
    reinterpret_cast<float4*>(s_acc[warp])[lane] = acc;   // STS.128
    if (lane == 0) s_w[warp] = wsum;                      // all lanes equal
    __syncthreads();

    // final reduce + fused EMA epilogue (threads 0..127 = columns)
    const int col = threadIdx.x;
    if (col < D) {
        float tot = 0.f, ws = 0.f;
#pragma unroll
        for (int k = 0; k < RED_WARPS; k++) { tot += s_acc[k][col]; ws += s_w[k]; }
        float p   = proto[c * D + col];
        float vec = tot / fmaxf(ws, 1e-8f);
        out[c * D + col] = (ws > 0.f) ? (MOM * p + (1.0f - MOM) * vec) : p;
    }

    // reset cursor for the next graph replay (zero-init covers call #1)
    if (threadIdx.x == 0) g_cursor[c * CPAD] = 0;
}

extern "C" void kernel_launch(void* const* d_in, const int* in_sizes, int n_in,
                              void* d_out, int out_size)
{
    const float* feats   = (const float*)d_in[0];
    const int*   labels  = (const int*)  d_in[1];
    const float* weights = (const float*)d_in[2];
    const float* proto   = (const float*)d_in[3];
    float*       out     = (float*)d_out;

    const int n = in_sizes[1];  // labels element count == N

    const int scat_grid = (n + SCAT_THREADS * SCAT_ILP - 1) / (SCAT_THREADS * SCAT_ILP);
    scatter_kernel<<<scat_grid, SCAT_THREADS>>>(labels, weights, n);
    reduce_kernel<<<C, RED_THREADS>>>(feats, proto, out);
}